// round 1
// baseline (speedup 1.0000x reference)
#include <cuda_runtime.h>
#include <cstddef>

#define NN 13
#define DD 16
#define EPB 16
#define NTHREADS 256
#define NLAYERS 4
#define NCH 4
#define NEG_SLOPE 0.01f
#define BN_EPS 1e-5f

struct Smem {
  float adj[EPB][NCH][NN][NN];   // staged adjacency, identity layout
  float x[EPB][NN][DD];          // per-element node features (reused for temp)
  float w0[NLAYERS][DD][DD];
  float b0[NLAYERS][DD];
  float w1[NLAYERS][DD][DD];
  float b1[NLAYERS][DD];
  float fc1[DD][DD]; float fc1b[DD];
  float fc2[DD][DD]; float fc2b[DD];
  float dec[NCH][DD][DD]; float decb[NCH][DD];
  float wi[NN][DD];
  float bnia[NLAYERS][NN]; float bnib[NLAYERS][NN];
  float bnoa[NLAYERS][NN]; float bnob[NLAYERS][NN];
  float epsp[NLAYERS];
};

__device__ __forceinline__ float leaky(float v) {
  return v >= 0.f ? v : NEG_SLOPE * v;
}

extern "C" __global__ void __launch_bounds__(NTHREADS, 2)
vae_kernel(const float* __restrict__ g_adj, const float* __restrict__ g_wi,
           const float* __restrict__ g_eps,
           const float* __restrict__ g_w0, const float* __restrict__ g_b0,
           const float* __restrict__ g_w1, const float* __restrict__ g_b1,
           const float* __restrict__ g_big, const float* __restrict__ g_bib,
           const float* __restrict__ g_bim, const float* __restrict__ g_biv,
           const float* __restrict__ g_bog, const float* __restrict__ g_bob,
           const float* __restrict__ g_bom, const float* __restrict__ g_bov,
           const float* __restrict__ g_fc1w, const float* __restrict__ g_fc1b,
           const float* __restrict__ g_fc2w, const float* __restrict__ g_fc2b,
           const float* __restrict__ g_decw, const float* __restrict__ g_decb,
           float* __restrict__ o_recon, float* __restrict__ o_mu,
           float* __restrict__ o_lv, int Btot)
{
  extern __shared__ unsigned char smem_raw[];
  Smem& s = *reinterpret_cast<Smem*>(smem_raw);
  const int tid = threadIdx.x;

  const int b0blk = blockIdx.x * EPB;
  const int nelem = (Btot - b0blk) < EPB ? (Btot - b0blk) : EPB;

  // ---- stage adjacency (coalesced float4) ----
  {
    const float4* src = reinterpret_cast<const float4*>(g_adj) +
                        (size_t)b0blk * (NCH * NN * NN / 2) / 2;
    float4* dst = reinterpret_cast<float4*>(&s.adj[0][0][0][0]);
    const int cnt = nelem * NCH * NN * NN / 4;   // 676 % 4 == 0
    for (int i = tid; i < cnt; i += NTHREADS) dst[i] = src[i];
  }
  // ---- stage weights / biases ----
  for (int i = tid; i < NLAYERS * DD * DD; i += NTHREADS) {
    (&s.w0[0][0][0])[i]  = g_w0[i];
    (&s.w1[0][0][0])[i]  = g_w1[i];
    (&s.dec[0][0][0])[i] = g_decw[i];
  }
  for (int i = tid; i < NLAYERS * DD; i += NTHREADS) {
    (&s.b0[0][0])[i]   = g_b0[i];
    (&s.b1[0][0])[i]   = g_b1[i];
    (&s.decb[0][0])[i] = g_decb[i];
  }
  for (int i = tid; i < DD * DD; i += NTHREADS) {
    (&s.fc1[0][0])[i] = g_fc1w[i];
    (&s.fc2[0][0])[i] = g_fc2w[i];
  }
  if (tid < DD) { s.fc1b[tid] = g_fc1b[tid]; s.fc2b[tid] = g_fc2b[tid]; }
  for (int i = tid; i < NN * DD; i += NTHREADS) (&s.wi[0][0])[i] = g_wi[i];
  if (tid < NLAYERS) s.epsp[tid] = g_eps[tid];
  // BN eval folded to affine: a = g * rsqrt(v+eps); b = beta - m*a
  for (int i = tid; i < NLAYERS * NN; i += NTHREADS) {
    float a = g_big[i] * rsqrtf(g_biv[i] + BN_EPS);
    (&s.bnia[0][0])[i] = a;
    (&s.bnib[0][0])[i] = g_bib[i] - g_bim[i] * a;
    float ao = g_bog[i] * rsqrtf(g_bov[i] + BN_EPS);
    (&s.bnoa[0][0])[i] = ao;
    (&s.bnob[0][0])[i] = g_bob[i] - g_bom[i] * ao;
  }
  __syncthreads();

  const int e = tid >> 4;          // element within block (half-warp group)
  const int n = tid & 15;          // node index; lanes 13..15 idle
  const bool act = (n < NN) && (e < nelem);
  const unsigned mask = (tid & 16) ? 0xFFFF0000u : 0x0000FFFFu;
  const int b = b0blk + e;

  float x[DD];
  // ---- initial embedding: x[n,d] = sum_m (sum_i adj[i,n,m]) * Wi[m,d] ----
  if (act) {
    #pragma unroll
    for (int d = 0; d < DD; d++) x[d] = 0.f;
    #pragma unroll
    for (int m = 0; m < NN; m++) {
      float am = s.adj[e][0][n][m] + s.adj[e][1][n][m]
               + s.adj[e][2][n][m] + s.adj[e][3][n][m];
      #pragma unroll
      for (int d = 0; d < DD; d++) x[d] += am * s.wi[m][d];
    }
    float4* xo = reinterpret_cast<float4*>(s.x[e][n]);
    #pragma unroll
    for (int q = 0; q < 4; q++)
      xo[q] = make_float4(x[4*q], x[4*q+1], x[4*q+2], x[4*q+3]);
  }
  __syncwarp(mask);

  // ---- GIN layers ----
  #pragma unroll 1
  for (int l = 0; l < NLAYERS; l++) {
    if (act) {
      float nb[DD];
      #pragma unroll
      for (int d = 0; d < DD; d++) nb[d] = 0.f;
      #pragma unroll
      for (int m = 0; m < NN; m++) {
        float a0 = s.adj[e][0][n][m], a1 = s.adj[e][1][n][m];
        float a2 = s.adj[e][2][n][m], a3 = s.adj[e][3][n][m];
        const float4* xm = reinterpret_cast<const float4*>(s.x[e][m]);
        float4 v0 = xm[0], v1 = xm[1], v2 = xm[2], v3 = xm[3];
        nb[0] += a0*v0.x;  nb[1] += a0*v0.y;  nb[2] += a0*v0.z;  nb[3] += a0*v0.w;
        nb[4] += a1*v1.x;  nb[5] += a1*v1.y;  nb[6] += a1*v1.z;  nb[7] += a1*v1.w;
        nb[8] += a2*v2.x;  nb[9] += a2*v2.y;  nb[10]+= a2*v2.z;  nb[11]+= a2*v2.w;
        nb[12]+= a3*v3.x;  nb[13]+= a3*v3.y;  nb[14]+= a3*v3.z;  nb[15]+= a3*v3.w;
      }
      const float ep = 1.f + s.epsp[l];
      float agg[DD];
      #pragma unroll
      for (int d = 0; d < DD; d++) agg[d] = ep * x[d] + nb[d];

      const float ai = s.bnia[l][n], bi = s.bnib[l][n];
      float h[DD];
      #pragma unroll
      for (int o = 0; o < DD; o++) {
        const float* wr = s.w0[l][o];
        float acc = s.b0[l][o];
        #pragma unroll
        for (int d = 0; d < DD; d++) acc += agg[d] * wr[d];
        h[o] = leaky(acc * ai + bi);
      }
      const float ao = s.bnoa[l][n], bo = s.bnob[l][n];
      #pragma unroll
      for (int o = 0; o < DD; o++) {
        const float* wr = s.w1[l][o];
        float acc = s.b1[l][o];
        #pragma unroll
        for (int d = 0; d < DD; d++) acc += h[d] * wr[d];
        x[o] = leaky(acc * ao + bo);
      }
    }
    __syncwarp(mask);   // all group reads of old x done
    if (act) {
      float4* xo = reinterpret_cast<float4*>(s.x[e][n]);
      #pragma unroll
      for (int q = 0; q < 4; q++)
        xo[q] = make_float4(x[4*q], x[4*q+1], x[4*q+2], x[4*q+3]);
    }
    __syncwarp(mask);   // new x visible
  }

  // ---- mu / logvar heads ----
  float mu[DD];
  if (act) {
    float lv[DD];
    #pragma unroll
    for (int o = 0; o < DD; o++) {
      float a1 = s.fc1b[o], a2 = s.fc2b[o];
      const float* w1r = s.fc1[o];
      const float* w2r = s.fc2[o];
      #pragma unroll
      for (int d = 0; d < DD; d++) { a1 += x[d] * w1r[d]; a2 += x[d] * w2r[d]; }
      mu[o] = a1; lv[o] = a2;
    }
    size_t base = ((size_t)b * NN + n) * DD;
    float4* mo = reinterpret_cast<float4*>(o_mu + base);
    float4* lo = reinterpret_cast<float4*>(o_lv + base);
    #pragma unroll
    for (int q = 0; q < 4; q++) {
      mo[q] = make_float4(mu[4*q], mu[4*q+1], mu[4*q+2], mu[4*q+3]);
      lo[q] = make_float4(lv[4*q], lv[4*q+1], lv[4*q+2], lv[4*q+3]);
    }
  }

  // ---- decoder: per k, temp = z @ dec_w[k]^T + dec_b[k]; recon = relu(T T^T) ----
  #pragma unroll 1
  for (int k = 0; k < NCH; k++) {
    float t[DD];
    __syncwarp(mask);   // previous k's recon reads done before overwriting s.x
    if (act) {
      #pragma unroll
      for (int d = 0; d < DD; d++) {
        const float* wr = s.dec[k][d];
        float acc = s.decb[k][d];
        #pragma unroll
        for (int l2 = 0; l2 < DD; l2++) acc += mu[l2] * wr[l2];
        t[d] = acc;
      }
      float4* xo = reinterpret_cast<float4*>(s.x[e][n]);
      #pragma unroll
      for (int q = 0; q < 4; q++)
        xo[q] = make_float4(t[4*q], t[4*q+1], t[4*q+2], t[4*q+3]);
    }
    __syncwarp(mask);
    if (act) {
      float* rp = o_recon + (((size_t)b * NCH + k) * NN + n) * NN;
      #pragma unroll
      for (int m = 0; m < NN; m++) {
        const float4* tm = reinterpret_cast<const float4*>(s.x[e][m]);
        float4 v0 = tm[0], v1 = tm[1], v2 = tm[2], v3 = tm[3];
        float acc = t[0]*v0.x + t[1]*v0.y + t[2]*v0.z + t[3]*v0.w
                  + t[4]*v1.x + t[5]*v1.y + t[6]*v1.z + t[7]*v1.w
                  + t[8]*v2.x + t[9]*v2.y + t[10]*v2.z + t[11]*v2.w
                  + t[12]*v3.x + t[13]*v3.y + t[14]*v3.z + t[15]*v3.w;
        rp[m] = fmaxf(acc, 0.f);
      }
    }
  }
}

extern "C" void kernel_launch(void* const* d_in, const int* in_sizes, int n_in,
                              void* d_out, int out_size) {
  const float* g_adj  = (const float*)d_in[0];
  const float* g_wi   = (const float*)d_in[1];
  const float* g_eps  = (const float*)d_in[2];
  const float* g_w0   = (const float*)d_in[3];
  const float* g_b0   = (const float*)d_in[4];
  const float* g_w1   = (const float*)d_in[5];
  const float* g_b1   = (const float*)d_in[6];
  const float* g_big  = (const float*)d_in[7];
  const float* g_bib  = (const float*)d_in[8];
  const float* g_bim  = (const float*)d_in[9];
  const float* g_biv  = (const float*)d_in[10];
  const float* g_bog  = (const float*)d_in[11];
  const float* g_bob  = (const float*)d_in[12];
  const float* g_bom  = (const float*)d_in[13];
  const float* g_bov  = (const float*)d_in[14];
  const float* g_fc1w = (const float*)d_in[15];
  const float* g_fc1b = (const float*)d_in[16];
  const float* g_fc2w = (const float*)d_in[17];
  const float* g_fc2b = (const float*)d_in[18];
  const float* g_decw = (const float*)d_in[19];
  const float* g_decb = (const float*)d_in[20];

  const int Btot = in_sizes[0] / (NCH * NN * NN);   // 32768
  float* out = (float*)d_out;
  float* o_recon = out;
  float* o_mu = out + (size_t)Btot * NCH * NN * NN;
  float* o_lv = o_mu + (size_t)Btot * NN * DD;

  cudaFuncSetAttribute((const void*)vae_kernel,
                       cudaFuncAttributeMaxDynamicSharedMemorySize,
                       (int)sizeof(Smem));
  int grid = (Btot + EPB - 1) / EPB;
  vae_kernel<<<grid, NTHREADS, sizeof(Smem)>>>(
      g_adj, g_wi, g_eps, g_w0, g_b0, g_w1, g_b1,
      g_big, g_bib, g_bim, g_biv, g_bog, g_bob, g_bom, g_bov,
      g_fc1w, g_fc1b, g_fc2w, g_fc2b, g_decw, g_decb,
      o_recon, o_mu, o_lv, Btot);
}